// round 1
// baseline (speedup 1.0000x reference)
#include <cuda_runtime.h>
#include <math.h>

// ---------------- problem constants ----------------
#define B       2
#define C       128
#define H0      384
#define W0      512
#define H1      192
#define W1      256
#define N0      (H0*W0)     // 196608
#define N1      (H1*W1)     // 49152
#define NTOT    (N0+N1)
#define K_KP    512
#define K_MATCH 128
#define CAP     32768
#define MKEEP   4096
#define THRESH  0.7f
#define INVTEMP 512.0f

// ---------------- device scratch (static — no allocations allowed) ----------------
__device__ float g_cand_score[4][CAP];
__device__ int   g_cand_idx[4][CAP];
__device__ int   g_cand_count[4];
__device__ float g_kp_score[4][K_KP];
__device__ int   g_kp_idx[4][K_KP];
__device__ float g_desc[4][C][K_KP];   // desc * score, row = img*2 + b
__device__ float g_loc[4][2][K_KP];    // [row][{r,c}][k]
__device__ float g_qk[4][C][K_KP];     // rows 0,1 = q (img1), rows 2,3 = k (img2)
__device__ float g_rel[B][K_KP][K_KP];
__device__ float g_ratio[B][K_KP];
__device__ float g_y[B][2][K_KP];

// ---------------- kernels ----------------
__global__ void reset_kernel() {
    if (threadIdx.x < 4) g_cand_count[threadIdx.x] = 0;
}

// fused score + 3x3 NMS + threshold -> candidate append
__global__ void score_kernel(const float* __restrict__ rep,
                             const float* __restrict__ rel,
                             int H, int W, int rowBase, int nOffset) {
    int t = blockIdx.x * blockDim.x + threadIdx.x;
    int HW = H * W;
    if (t >= B * HW) return;
    int b = t / HW, p = t - b * HW;
    int r = p / W, c = p - r * W;
    const float* repb = rep + b * HW;
    float v = repb[p];
    float e = rel[b * HW + p];
    float mean = sqrtf(v * e);
    if (mean < THRESH) return;
    // rep == maxpool3(rep)  <=>  no neighbor strictly greater
    bool ok = true;
    #pragma unroll
    for (int dr = -1; dr <= 1; ++dr) {
        int rr = r + dr;
        if (rr < 0 || rr >= H) continue;
        #pragma unroll
        for (int dc = -1; dc <= 1; ++dc) {
            if (dr == 0 && dc == 0) continue;
            int cc = c + dc;
            if (cc < 0 || cc >= W) continue;
            if (repb[rr * W + cc] > v) ok = false;
        }
    }
    if (!ok) return;
    int row = rowBase + b;
    int pos = atomicAdd(&g_cand_count[row], 1);
    if (pos < CAP) {
        g_cand_score[row][pos] = mean;
        g_cand_idx[row][pos]   = nOffset + p;
    }
}

// per-row top-512: histogram prune then exact rank-count (jax top_k semantics:
// descending, ties -> lowest index first)
__global__ void topk_kernel() {
    __shared__ int   hist[1024];
    __shared__ float ks_[MKEEP];
    __shared__ int   ki_[MKEEP];
    __shared__ int   s_thr, s_keep;
    int row = blockIdx.x;
    int tid = threadIdx.x;              // 1024 threads
    int count = g_cand_count[row];
    if (count > CAP) count = CAP;

    hist[tid] = 0;
    if (tid == 0) { s_thr = 0; s_keep = 0; }
    __syncthreads();

    const float SCL = 1024.0f / 0.3f;
    for (int i = tid; i < count; i += 1024) {
        float s = g_cand_score[row][i];
        int bb = (int)((s - THRESH) * SCL);
        bb = max(0, min(1023, bb));
        atomicAdd(&hist[bb], 1);
    }
    __syncthreads();

    // suffix counts: each thread t computes sum(hist[t..1023])
    int cge = 0;
    for (int b2 = tid; b2 < 1024; ++b2) cge += hist[b2];
    int cge_next = cge - hist[tid];
    if (cge >= K_KP && cge_next < K_KP) s_thr = tid;   // unique writer
    __syncthreads();

    int thr = s_thr;
    for (int i = tid; i < count; i += 1024) {
        float s = g_cand_score[row][i];
        int bb = (int)((s - THRESH) * SCL);
        bb = max(0, min(1023, bb));
        if (bb >= thr) {
            int p = atomicAdd(&s_keep, 1);
            if (p < MKEEP) { ks_[p] = s; ki_[p] = g_cand_idx[row][i]; }
        }
    }
    __syncthreads();
    int kept = min(s_keep, MKEEP);

    for (int i = tid; i < kept; i += 1024) {
        float si = ks_[i]; int ii = ki_[i];
        int rank = 0;
        for (int j = 0; j < kept; ++j) {
            float sj = ks_[j];
            rank += (sj > si) || (sj == si && ki_[j] < ii);
        }
        if (rank < K_KP) { g_kp_score[row][rank] = si; g_kp_idx[row][rank] = ii; }
    }
    __syncthreads();
    if (kept < K_KP) {   // degenerate padding (mirrors -1 fills; won't trigger here)
        for (int r2 = kept + tid; r2 < K_KP; r2 += 1024) {
            g_kp_score[row][r2] = -1.0f;
            g_kp_idx[row][r2]   = r2 - kept;
        }
    }
}

// gather descriptors * score + locations
__global__ void gather_kernel(const float* __restrict__ d1s0, const float* __restrict__ d1s1,
                              const float* __restrict__ d2s0, const float* __restrict__ d2s1) {
    int kpos = blockIdx.x;        // 512
    int row  = blockIdx.y;        // 4
    int ch   = threadIdx.x;       // 128
    int img  = row >> 1, b = row & 1;
    int idx  = g_kp_idx[row][kpos];
    float sc = g_kp_score[row][kpos];
    const float* dsc; int HW, W, p; float scale;
    if (idx < N0) { dsc = img ? d2s0 : d1s0; HW = N0; W = W0; p = idx;       scale = 1.0f; }
    else          { dsc = img ? d2s1 : d1s1; HW = N1; W = W1; p = idx - N0;  scale = 2.0f; }
    float val = dsc[(b * C + ch) * HW + p] * sc;
    g_desc[row][ch][kpos] = val;
    if (ch < 2) {
        int r = p / W, c = p - r * W;
        g_loc[row][ch][kpos] = (ch == 0 ? (float)r : (float)c) * scale;
    }
}

// apply Wq (rows 0,1) / Wk (rows 2,3): g_qk[row][:, n] = W * g_desc[row][:, n]
__global__ void wqk_kernel(const float* __restrict__ Wq, const float* __restrict__ Wk) {
    __shared__ float ds[C][16];
    int row = blockIdx.y;
    int n0  = blockIdx.x * 16;
    const float* W = (row < 2) ? Wq : Wk;
    int tid = threadIdx.x;   // 128
    for (int i = tid; i < C * 16; i += 128) {
        int j = i >> 4, t = i & 15;
        ds[j][t] = g_desc[row][j][n0 + t];
    }
    __syncthreads();
    float acc[16];
    #pragma unroll
    for (int t = 0; t < 16; ++t) acc[t] = 0.0f;
    const float* wrow = W + tid * C;
    for (int j = 0; j < C; ++j) {
        float w = wrow[j];
        #pragma unroll
        for (int t = 0; t < 16; ++t) acc[t] += w * ds[j][t];
    }
    #pragma unroll
    for (int t = 0; t < 16; ++t) g_qk[row][tid][n0 + t] = acc[t];
}

// rel[b][n][m] = sum_c q[b][c][n] * k[b][c][m]  (64x64 tiles, fp32)
__global__ void rel_kernel() {
    __shared__ float qs[32][64];
    __shared__ float ks2[32][64];
    int b  = blockIdx.z;
    int n0 = blockIdx.y * 64, m0 = blockIdx.x * 64;
    int tid = threadIdx.x;              // 256
    int tx = tid & 15, ty = tid >> 4;   // 16x16
    float acc[4][4];
    #pragma unroll
    for (int i = 0; i < 4; ++i)
        #pragma unroll
        for (int j = 0; j < 4; ++j) acc[i][j] = 0.0f;

    for (int c0 = 0; c0 < C; c0 += 32) {
        for (int i = tid; i < 32 * 64; i += 256) {
            int cc = i >> 6, nn = i & 63;
            qs[cc][nn]  = g_qk[b][c0 + cc][n0 + nn];
            ks2[cc][nn] = g_qk[2 + b][c0 + cc][m0 + nn];
        }
        __syncthreads();
        #pragma unroll
        for (int cc = 0; cc < 32; ++cc) {
            float qv[4], kv[4];
            #pragma unroll
            for (int i = 0; i < 4; ++i) qv[i] = qs[cc][ty * 4 + i];
            #pragma unroll
            for (int j = 0; j < 4; ++j) kv[j] = ks2[cc][tx * 4 + j];
            #pragma unroll
            for (int i = 0; i < 4; ++i)
                #pragma unroll
                for (int j = 0; j < 4; ++j) acc[i][j] += qv[i] * kv[j];
        }
        __syncthreads();
    }
    #pragma unroll
    for (int i = 0; i < 4; ++i)
        #pragma unroll
        for (int j = 0; j < 4; ++j)
            g_rel[b][n0 + ty * 4 + i][m0 + tx * 4 + j] = acc[i][j];
}

// per-row: top2 -> acos ratio; softmax(rel*512) weighted loc2 -> y
__global__ void match_kernel(const float* __restrict__ Wv) {
    int b    = blockIdx.y;
    int warp = threadIdx.x >> 5, lane = threadIdx.x & 31;
    int n = blockIdx.x * 8 + warp;
    const float* relrow = &g_rel[b][n][0];

    float m1 = -2.0f, m2 = -2.0f;
    for (int m = lane; m < K_KP; m += 32) {
        float v = relrow[m];
        if (v > m1) { m2 = m1; m1 = v; }
        else if (v > m2) m2 = v;
    }
    #pragma unroll
    for (int off = 16; off; off >>= 1) {
        float o1 = __shfl_down_sync(0xffffffffu, m1, off);
        float o2 = __shfl_down_sync(0xffffffffu, m2, off);
        if (o1 > m1) { m2 = fmaxf(m1, o2); m1 = o1; }
        else         { m2 = fmaxf(m2, o1); }
    }
    m1 = __shfl_sync(0xffffffffu, m1, 0);
    m2 = __shfl_sync(0xffffffffu, m2, 0);

    float wv00 = Wv[0], wv01 = Wv[1], wv10 = Wv[2], wv11 = Wv[3];
    int krow = 2 + b;
    float sw = 0.0f, y0 = 0.0f, y1 = 0.0f;
    for (int m = lane; m < K_KP; m += 32) {
        float v = relrow[m];
        float w = expf(INVTEMP * (v - m1));
        float l0 = g_loc[krow][0][m], l1 = g_loc[krow][1][m];
        sw += w;
        y0 += w * (wv00 * l0 + wv01 * l1);
        y1 += w * (wv10 * l0 + wv11 * l1);
    }
    #pragma unroll
    for (int off = 16; off; off >>= 1) {
        sw += __shfl_down_sync(0xffffffffu, sw, off);
        y0 += __shfl_down_sync(0xffffffffu, y0, off);
        y1 += __shfl_down_sync(0xffffffffu, y1, off);
    }
    if (lane == 0) {
        float a1 = acosf(fminf(fmaxf(m1, -1.0f), 1.0f));
        float a2 = acosf(fminf(fmaxf(m2, -1.0f), 1.0f));
        g_ratio[b][n] = a1 / a2;
        g_y[b][0][n] = y0 / sw;
        g_y[b][1][n] = y1 / sw;
    }
}

// final top-128 by smallest ratio (stable rank), write [B,4,128]
__global__ void final_kernel(float* __restrict__ out) {
    __shared__ float rs[K_KP];
    int b = blockIdx.x, tid = threadIdx.x;  // 512
    rs[tid] = g_ratio[b][tid];
    __syncthreads();
    float ri = rs[tid];
    int rank = 0;
    for (int j = 0; j < K_KP; ++j) {
        float rj = rs[j];
        rank += (rj < ri) || (rj == ri && j < tid);
    }
    if (rank < K_MATCH) {
        out[(b * 4 + 0) * K_MATCH + rank] = g_loc[b][0][tid];
        out[(b * 4 + 1) * K_MATCH + rank] = g_loc[b][1][tid];
        out[(b * 4 + 2) * K_MATCH + rank] = g_y[b][0][tid];
        out[(b * 4 + 3) * K_MATCH + rank] = g_y[b][1][tid];
    }
}

// ---------------- launch ----------------
extern "C" void kernel_launch(void* const* d_in, const int* in_sizes, int n_in,
                              void* d_out, int out_size) {
    const float* rep1_s0 = (const float*)d_in[0];
    const float* rel1_s0 = (const float*)d_in[1];
    const float* desc1_s0 = (const float*)d_in[2];
    const float* rep1_s1 = (const float*)d_in[3];
    const float* rel1_s1 = (const float*)d_in[4];
    const float* desc1_s1 = (const float*)d_in[5];
    const float* rep2_s0 = (const float*)d_in[6];
    const float* rel2_s0 = (const float*)d_in[7];
    const float* desc2_s0 = (const float*)d_in[8];
    const float* rep2_s1 = (const float*)d_in[9];
    const float* rel2_s1 = (const float*)d_in[10];
    const float* desc2_s1 = (const float*)d_in[11];
    const float* Wq = (const float*)d_in[12];
    const float* Wk = (const float*)d_in[13];
    const float* Wv = (const float*)d_in[14];
    float* out = (float*)d_out;

    reset_kernel<<<1, 32>>>();

    int g0 = (B * N0 + 255) / 256;
    int g1 = (B * N1 + 255) / 256;
    score_kernel<<<g0, 256>>>(rep1_s0, rel1_s0, H0, W0, 0, 0);
    score_kernel<<<g1, 256>>>(rep1_s1, rel1_s1, H1, W1, 0, N0);
    score_kernel<<<g0, 256>>>(rep2_s0, rel2_s0, H0, W0, 2, 0);
    score_kernel<<<g1, 256>>>(rep2_s1, rel2_s1, H1, W1, 2, N0);

    topk_kernel<<<4, 1024>>>();

    gather_kernel<<<dim3(K_KP, 4), C>>>(desc1_s0, desc1_s1, desc2_s0, desc2_s1);

    wqk_kernel<<<dim3(K_KP / 16, 4), C>>>(Wq, Wk);

    rel_kernel<<<dim3(8, 8, B), 256>>>();

    match_kernel<<<dim3(K_KP / 8, B), 256>>>(Wv);

    final_kernel<<<B, K_KP>>>(out);
}

// round 2
// speedup vs baseline: 1.3098x; 1.3098x over previous
#include <cuda_runtime.h>
#include <math.h>

// ---------------- problem constants ----------------
#define B       2
#define C       128
#define H0      384
#define W0      512
#define H1      192
#define W1      256
#define N0      (H0*W0)     // 196608
#define N1      (H1*W1)     // 49152
#define K_KP    512
#define K_MATCH 128
#define CAP     32768
#define MKEEP   4096
#define THRESH  0.7f
#define INVTEMP 512.0f

// ---------------- device scratch ----------------
__device__ float g_cand_score[4][CAP];
__device__ int   g_cand_idx[4][CAP];
__device__ int   g_cand_count[4];
__device__ float g_kp_score[4][K_KP];
__device__ int   g_kp_idx[4][K_KP];
__device__ float g_loc[4][2][K_KP];    // [row][{r,c}][k]
__device__ float g_qk[4][C][K_KP];     // rows 0,1 = q (img1), rows 2,3 = k (img2)
__device__ float g_rel[B][K_KP][K_KP];
__device__ float g_ratio[B][K_KP];
__device__ float g_y[B][2][K_KP];

// ---------------- kernels ----------------
__global__ void reset_kernel() {
    if (threadIdx.x < 4) g_cand_count[threadIdx.x] = 0;
}

// Fused score + 3x3 NMS over all 8 (img, scale, batch) slices.
// Block: 256 threads = 32x8 pixel tile; smem halo tile for rep;
// block-aggregated candidate append (one global atomic per block).
__global__ void score_all_kernel(const float* __restrict__ rep10, const float* __restrict__ rel10,
                                 const float* __restrict__ rep11, const float* __restrict__ rel11,
                                 const float* __restrict__ rep20, const float* __restrict__ rel20,
                                 const float* __restrict__ rep21, const float* __restrict__ rel21) {
    int z    = blockIdx.z;           // 0..7
    int img  = z >> 2;               // 0: image1, 1: image2
    int scal = (z >> 1) & 1;         // 0: s0, 1: s1
    int b    = z & 1;
    const float *rep, *rel;
    int H, W, nOff;
    if (scal == 0) { rep = img ? rep20 : rep10; rel = img ? rel20 : rel10; H = H0; W = W0; nOff = 0;  }
    else           { rep = img ? rep21 : rep11; rel = img ? rel21 : rel11; H = H1; W = W1; nOff = N0; }
    if ((int)blockIdx.x * 32 >= W || (int)blockIdx.y * 8 >= H) return;
    int row = img * 2 + b;

    __shared__ float s[10][34];
    __shared__ float c_sc[256];
    __shared__ int   c_ix[256];
    __shared__ int   c_cnt, c_base;

    int tid = threadIdx.x;
    int tx = tid & 31, ty = tid >> 5;            // 32 x 8
    int gx0 = blockIdx.x * 32, gy0 = blockIdx.y * 8;
    const float* repb = rep + b * (H * W);

    if (tid == 0) c_cnt = 0;
    // halo tile load: 34 x 10
    for (int i = tid; i < 34 * 10; i += 256) {
        int ly = i / 34, lx = i - ly * 34;
        int gy = gy0 + ly - 1, gx = gx0 + lx - 1;
        float v = -INFINITY;
        if (gy >= 0 && gy < H && gx >= 0 && gx < W) v = repb[gy * W + gx];
        s[ly][lx] = v;
    }
    __syncthreads();

    int gx = gx0 + tx, gy = gy0 + ty;            // exact tiling, no bounds check
    float v = s[ty + 1][tx + 1];
    float e = rel[b * (H * W) + gy * W + gx];
    float mean = sqrtf(v * e);
    bool pass = (mean >= THRESH);
    if (pass) {
        // local max: no neighbor strictly greater
        float nb = fmaxf(fmaxf(s[ty][tx],     s[ty][tx + 1]),
                         fmaxf(s[ty][tx + 2], s[ty + 1][tx]));
        nb = fmaxf(nb, fmaxf(fmaxf(s[ty + 1][tx + 2], s[ty + 2][tx]),
                             fmaxf(s[ty + 2][tx + 1], s[ty + 2][tx + 2])));
        pass = !(nb > v);
    }
    if (pass) {
        int p = atomicAdd(&c_cnt, 1);
        c_sc[p] = mean;
        c_ix[p] = nOff + gy * W + gx;
    }
    __syncthreads();
    int cnt = c_cnt;
    if (cnt == 0) return;
    if (tid == 0) c_base = atomicAdd(&g_cand_count[row], cnt);
    __syncthreads();
    int base = c_base;
    if (tid < cnt) {
        int pos = base + tid;
        if (pos < CAP) {
            g_cand_score[row][pos] = c_sc[tid];
            g_cand_idx[row][pos]   = c_ix[tid];
        }
    }
}

// per-row top-512: histogram prune then exact rank-count (jax top_k semantics:
// descending, ties -> lowest index first)
__global__ void topk_kernel() {
    __shared__ int   hist[1024];
    __shared__ float ks_[MKEEP];
    __shared__ int   ki_[MKEEP];
    __shared__ int   s_thr, s_keep;
    int row = blockIdx.x;
    int tid = threadIdx.x;              // 1024 threads
    int count = g_cand_count[row];
    if (count > CAP) count = CAP;

    hist[tid] = 0;
    if (tid == 0) { s_thr = 0; s_keep = 0; }
    __syncthreads();

    const float SCL = 1024.0f / 0.3f;
    for (int i = tid; i < count; i += 1024) {
        float sc = g_cand_score[row][i];
        int bb = (int)((sc - THRESH) * SCL);
        bb = max(0, min(1023, bb));
        atomicAdd(&hist[bb], 1);
    }
    __syncthreads();

    int cge = 0;
    for (int b2 = tid; b2 < 1024; ++b2) cge += hist[b2];
    int cge_next = cge - hist[tid];
    if (cge >= K_KP && cge_next < K_KP) s_thr = tid;   // unique writer
    __syncthreads();

    int thr = s_thr;
    for (int i = tid; i < count; i += 1024) {
        float sc = g_cand_score[row][i];
        int bb = (int)((sc - THRESH) * SCL);
        bb = max(0, min(1023, bb));
        if (bb >= thr) {
            int p = atomicAdd(&s_keep, 1);
            if (p < MKEEP) { ks_[p] = sc; ki_[p] = g_cand_idx[row][i]; }
        }
    }
    __syncthreads();
    int kept = min(s_keep, MKEEP);

    for (int i = tid; i < kept; i += 1024) {
        float si = ks_[i]; int ii = ki_[i];
        int rank = 0;
        for (int j = 0; j < kept; ++j) {
            float sj = ks_[j];
            rank += (sj > si) || (sj == si && ki_[j] < ii);
        }
        if (rank < K_KP) { g_kp_score[row][rank] = si; g_kp_idx[row][rank] = ii; }
    }
    __syncthreads();
    if (kept < K_KP) {   // degenerate padding; won't trigger on this data
        for (int r2 = kept + tid; r2 < K_KP; r2 += 1024) {
            g_kp_score[row][r2] = -1.0f;
            g_kp_idx[row][r2]   = r2 - kept;
        }
    }
}

// Fused: gather desc*score at keypoints + apply Wq/Wk + write locations.
// Block: 128 threads (= channels), handles 16 keypoints of one row.
__global__ void gather_wqk_kernel(const float* __restrict__ d1s0, const float* __restrict__ d1s1,
                                  const float* __restrict__ d2s0, const float* __restrict__ d2s1,
                                  const float* __restrict__ Wq,  const float* __restrict__ Wk) {
    __shared__ float ds[C][17];
    __shared__ int   sp[16];
    __shared__ float ss[16];
    int n0  = blockIdx.x * 16;
    int row = blockIdx.y;
    int img = row >> 1, b = row & 1;
    int tid = threadIdx.x;    // 128

    if (tid < 16) {
        int idx  = g_kp_idx[row][n0 + tid];
        float sc = g_kp_score[row][n0 + tid];
        sp[tid] = idx; ss[tid] = sc;
        int W, p; float scale;
        if (idx < N0) { W = W0; p = idx;      scale = 1.0f; }
        else          { W = W1; p = idx - N0; scale = 2.0f; }
        int r = p / W, c = p - r * W;
        g_loc[row][0][n0 + tid] = (float)r * scale;
        g_loc[row][1][n0 + tid] = (float)c * scale;
    }
    __syncthreads();

    #pragma unroll
    for (int t = 0; t < 16; ++t) {
        int idx = sp[t]; float sc = ss[t];
        const float* dsc; int HW, p;
        if (idx < N0) { dsc = img ? d2s0 : d1s0; HW = N0; p = idx; }
        else          { dsc = img ? d2s1 : d1s1; HW = N1; p = idx - N0; }
        ds[tid][t] = __ldg(&dsc[(b * C + tid) * HW + p]) * sc;
    }
    __syncthreads();

    const float* Wm = (row < 2) ? Wq : Wk;
    float acc[16];
    #pragma unroll
    for (int t = 0; t < 16; ++t) acc[t] = 0.0f;
    const float* wrow = Wm + tid * C;
    #pragma unroll 4
    for (int j = 0; j < C; ++j) {
        float w = __ldg(&wrow[j]);
        #pragma unroll
        for (int t = 0; t < 16; ++t) acc[t] += w * ds[j][t];
    }
    #pragma unroll
    for (int t = 0; t < 16; ++t) g_qk[row][tid][n0 + t] = acc[t];
}

// rel[b][n][m] = sum_c q[b][c][n] * k[b][c][m]  (64x64 tiles, fp32)
__global__ void rel_kernel() {
    __shared__ float qs[32][64];
    __shared__ float ks2[32][64];
    int b  = blockIdx.z;
    int n0 = blockIdx.y * 64, m0 = blockIdx.x * 64;
    int tid = threadIdx.x;              // 256
    int tx = tid & 15, ty = tid >> 4;   // 16x16
    float acc[4][4];
    #pragma unroll
    for (int i = 0; i < 4; ++i)
        #pragma unroll
        for (int j = 0; j < 4; ++j) acc[i][j] = 0.0f;

    for (int c0 = 0; c0 < C; c0 += 32) {
        for (int i = tid; i < 32 * 64; i += 256) {
            int cc = i >> 6, nn = i & 63;
            qs[cc][nn]  = g_qk[b][c0 + cc][n0 + nn];
            ks2[cc][nn] = g_qk[2 + b][c0 + cc][m0 + nn];
        }
        __syncthreads();
        #pragma unroll
        for (int cc = 0; cc < 32; ++cc) {
            float qv[4], kv[4];
            #pragma unroll
            for (int i = 0; i < 4; ++i) qv[i] = qs[cc][ty * 4 + i];
            #pragma unroll
            for (int j = 0; j < 4; ++j) kv[j] = ks2[cc][tx * 4 + j];
            #pragma unroll
            for (int i = 0; i < 4; ++i)
                #pragma unroll
                for (int j = 0; j < 4; ++j) acc[i][j] += qv[i] * kv[j];
        }
        __syncthreads();
    }
    #pragma unroll
    for (int i = 0; i < 4; ++i)
        #pragma unroll
        for (int j = 0; j < 4; ++j)
            g_rel[b][n0 + ty * 4 + i][m0 + tx * 4 + j] = acc[i][j];
}

// per-row: top2 -> acos ratio; softmax(rel*512) weighted loc2 -> y
__global__ void match_kernel(const float* __restrict__ Wv) {
    int b    = blockIdx.y;
    int warp = threadIdx.x >> 5, lane = threadIdx.x & 31;
    int n = blockIdx.x * 8 + warp;
    const float* relrow = &g_rel[b][n][0];

    float m1 = -2.0f, m2 = -2.0f;
    for (int m = lane; m < K_KP; m += 32) {
        float v = relrow[m];
        if (v > m1) { m2 = m1; m1 = v; }
        else if (v > m2) m2 = v;
    }
    #pragma unroll
    for (int off = 16; off; off >>= 1) {
        float o1 = __shfl_down_sync(0xffffffffu, m1, off);
        float o2 = __shfl_down_sync(0xffffffffu, m2, off);
        if (o1 > m1) { m2 = fmaxf(m1, o2); m1 = o1; }
        else         { m2 = fmaxf(m2, o1); }
    }
    m1 = __shfl_sync(0xffffffffu, m1, 0);
    m2 = __shfl_sync(0xffffffffu, m2, 0);

    float wv00 = Wv[0], wv01 = Wv[1], wv10 = Wv[2], wv11 = Wv[3];
    int krow = 2 + b;
    float sw = 0.0f, y0 = 0.0f, y1 = 0.0f;
    for (int m = lane; m < K_KP; m += 32) {
        float v = relrow[m];
        float w = expf(INVTEMP * (v - m1));
        float l0 = g_loc[krow][0][m], l1 = g_loc[krow][1][m];
        sw += w;
        y0 += w * (wv00 * l0 + wv01 * l1);
        y1 += w * (wv10 * l0 + wv11 * l1);
    }
    #pragma unroll
    for (int off = 16; off; off >>= 1) {
        sw += __shfl_down_sync(0xffffffffu, sw, off);
        y0 += __shfl_down_sync(0xffffffffu, y0, off);
        y1 += __shfl_down_sync(0xffffffffu, y1, off);
    }
    if (lane == 0) {
        float a1 = acosf(fminf(fmaxf(m1, -1.0f), 1.0f));
        float a2 = acosf(fminf(fmaxf(m2, -1.0f), 1.0f));
        g_ratio[b][n] = a1 / a2;
        g_y[b][0][n] = y0 / sw;
        g_y[b][1][n] = y1 / sw;
    }
}

// final top-128 by smallest ratio (stable rank), write [B,4,128]
__global__ void final_kernel(float* __restrict__ out) {
    __shared__ float rs[K_KP];
    int b = blockIdx.x, tid = threadIdx.x;  // 512
    rs[tid] = g_ratio[b][tid];
    __syncthreads();
    float ri = rs[tid];
    int rank = 0;
    for (int j = 0; j < K_KP; ++j) {
        float rj = rs[j];
        rank += (rj < ri) || (rj == ri && j < tid);
    }
    if (rank < K_MATCH) {
        out[(b * 4 + 0) * K_MATCH + rank] = g_loc[b][0][tid];
        out[(b * 4 + 1) * K_MATCH + rank] = g_loc[b][1][tid];
        out[(b * 4 + 2) * K_MATCH + rank] = g_y[b][0][tid];
        out[(b * 4 + 3) * K_MATCH + rank] = g_y[b][1][tid];
    }
}

// ---------------- launch ----------------
extern "C" void kernel_launch(void* const* d_in, const int* in_sizes, int n_in,
                              void* d_out, int out_size) {
    const float* rep1_s0 = (const float*)d_in[0];
    const float* rel1_s0 = (const float*)d_in[1];
    const float* desc1_s0 = (const float*)d_in[2];
    const float* rep1_s1 = (const float*)d_in[3];
    const float* rel1_s1 = (const float*)d_in[4];
    const float* desc1_s1 = (const float*)d_in[5];
    const float* rep2_s0 = (const float*)d_in[6];
    const float* rel2_s0 = (const float*)d_in[7];
    const float* desc2_s0 = (const float*)d_in[8];
    const float* rep2_s1 = (const float*)d_in[9];
    const float* rel2_s1 = (const float*)d_in[10];
    const float* desc2_s1 = (const float*)d_in[11];
    const float* Wq = (const float*)d_in[12];
    const float* Wk = (const float*)d_in[13];
    const float* Wv = (const float*)d_in[14];
    float* out = (float*)d_out;

    reset_kernel<<<1, 32>>>();

    // grid sized for the big map; small-map blocks early-exit
    score_all_kernel<<<dim3(W0 / 32, H0 / 8, 8), 256>>>(
        rep1_s0, rel1_s0, rep1_s1, rel1_s1, rep2_s0, rel2_s0, rep2_s1, rel2_s1);

    topk_kernel<<<4, 1024>>>();

    gather_wqk_kernel<<<dim3(K_KP / 16, 4), C>>>(desc1_s0, desc1_s1, desc2_s0, desc2_s1, Wq, Wk);

    rel_kernel<<<dim3(8, 8, B), 256>>>();

    match_kernel<<<dim3(K_KP / 8, B), 256>>>(Wv);

    final_kernel<<<B, K_KP>>>(out);
}

// round 3
// speedup vs baseline: 1.3543x; 1.0340x over previous
#include <cuda_runtime.h>
#include <math.h>

// ---------------- problem constants ----------------
#define B       2
#define C       128
#define H0      384
#define W0      512
#define H1      192
#define W1      256
#define N0      (H0*W0)     // 196608
#define N1      (H1*W1)     // 49152
#define K_KP    512
#define K_MATCH 128
#define CAP     32768
#define MKEEP   4096
#define THRESH  0.7f
#define INVTEMP 512.0f

// ---------------- device scratch ----------------
__device__ float g_cand_score[4][CAP];
__device__ int   g_cand_idx[4][CAP];
__device__ int   g_cand_count[4];
__device__ float g_kp_score[4][K_KP];
__device__ int   g_kp_idx[4][K_KP];
__device__ float g_desc[4][C][K_KP];   // gathered desc * score
__device__ float g_loc[4][2][K_KP];    // [row][{r,c}][k]
__device__ float g_qk[4][C][K_KP];     // rows 0,1 = q (img1), rows 2,3 = k (img2)
__device__ float g_rel[B][K_KP][K_KP];
__device__ float g_ratio[B][K_KP];
__device__ float g_y[B][2][K_KP];

// ---------------- kernels ----------------

// Fused score + 3x3 NMS over all 8 (img, scale, batch) slices.
// Block: 256 threads = 32x8 pixel tile; smem halo tile for rep;
// block-aggregated candidate append (one global atomic per block).
__global__ void score_all_kernel(const float* __restrict__ rep10, const float* __restrict__ rel10,
                                 const float* __restrict__ rep11, const float* __restrict__ rel11,
                                 const float* __restrict__ rep20, const float* __restrict__ rel20,
                                 const float* __restrict__ rep21, const float* __restrict__ rel21) {
    int z    = blockIdx.z;           // 0..7
    int img  = z >> 2;
    int scal = (z >> 1) & 1;
    int b    = z & 1;
    const float *rep, *rel;
    int H, W, nOff;
    if (scal == 0) { rep = img ? rep20 : rep10; rel = img ? rel20 : rel10; H = H0; W = W0; nOff = 0;  }
    else           { rep = img ? rep21 : rep11; rel = img ? rel21 : rel11; H = H1; W = W1; nOff = N0; }
    if ((int)blockIdx.x * 32 >= W || (int)blockIdx.y * 8 >= H) return;
    int row = img * 2 + b;

    __shared__ float s[10][34];
    __shared__ float c_sc[256];
    __shared__ int   c_ix[256];
    __shared__ int   c_cnt, c_base;

    int tid = threadIdx.x;
    int tx = tid & 31, ty = tid >> 5;            // 32 x 8
    int gx0 = blockIdx.x * 32, gy0 = blockIdx.y * 8;
    const float* repb = rep + b * (H * W);

    if (tid == 0) c_cnt = 0;
    for (int i = tid; i < 34 * 10; i += 256) {
        int ly = i / 34, lx = i - ly * 34;
        int gy = gy0 + ly - 1, gx = gx0 + lx - 1;
        float v = -INFINITY;
        if (gy >= 0 && gy < H && gx >= 0 && gx < W) v = repb[gy * W + gx];
        s[ly][lx] = v;
    }
    __syncthreads();

    int gx = gx0 + tx, gy = gy0 + ty;            // exact tiling, no bounds check
    float v = s[ty + 1][tx + 1];
    float e = rel[b * (H * W) + gy * W + gx];
    float mean = sqrtf(v * e);
    bool pass = (mean >= THRESH);
    if (pass) {
        float nb = fmaxf(fmaxf(s[ty][tx],     s[ty][tx + 1]),
                         fmaxf(s[ty][tx + 2], s[ty + 1][tx]));
        nb = fmaxf(nb, fmaxf(fmaxf(s[ty + 1][tx + 2], s[ty + 2][tx]),
                             fmaxf(s[ty + 2][tx + 1], s[ty + 2][tx + 2])));
        pass = !(nb > v);
    }
    if (pass) {
        int p = atomicAdd(&c_cnt, 1);
        c_sc[p] = mean;
        c_ix[p] = nOff + gy * W + gx;
    }
    __syncthreads();
    int cnt = c_cnt;
    if (cnt == 0) return;
    if (tid == 0) c_base = atomicAdd(&g_cand_count[row], cnt);
    __syncthreads();
    int base = c_base;
    if (tid < cnt) {
        int pos = base + tid;
        if (pos < CAP) {
            g_cand_score[row][pos] = c_sc[tid];
            g_cand_idx[row][pos]   = c_ix[tid];
        }
    }
}

// per-row top-512: histogram prune then exact rank-count (jax top_k semantics:
// descending, ties -> lowest index first)
__global__ void topk_kernel() {
    __shared__ int   hist[1024];
    __shared__ float ks_[MKEEP];
    __shared__ int   ki_[MKEEP];
    __shared__ int   s_thr, s_keep;
    int row = blockIdx.x;
    int tid = threadIdx.x;              // 1024 threads
    int count = g_cand_count[row];
    if (count > CAP) count = CAP;

    hist[tid] = 0;
    if (tid == 0) { s_thr = 0; s_keep = 0; }
    __syncthreads();

    const float SCL = 1024.0f / 0.3f;
    for (int i = tid; i < count; i += 1024) {
        float sc = g_cand_score[row][i];
        int bb = (int)((sc - THRESH) * SCL);
        bb = max(0, min(1023, bb));
        atomicAdd(&hist[bb], 1);
    }
    __syncthreads();

    int cge = 0;
    for (int b2 = tid; b2 < 1024; ++b2) cge += hist[b2];
    int cge_next = cge - hist[tid];
    if (cge >= K_KP && cge_next < K_KP) s_thr = tid;   // unique writer
    __syncthreads();

    int thr = s_thr;
    for (int i = tid; i < count; i += 1024) {
        float sc = g_cand_score[row][i];
        int bb = (int)((sc - THRESH) * SCL);
        bb = max(0, min(1023, bb));
        if (bb >= thr) {
            int p = atomicAdd(&s_keep, 1);
            if (p < MKEEP) { ks_[p] = sc; ki_[p] = g_cand_idx[row][i]; }
        }
    }
    __syncthreads();
    int kept = min(s_keep, MKEEP);

    for (int i = tid; i < kept; i += 1024) {
        float si = ks_[i]; int ii = ki_[i];
        int rank = 0;
        for (int j = 0; j < kept; ++j) {
            float sj = ks_[j];
            rank += (sj > si) || (sj == si && ki_[j] < ii);
        }
        if (rank < K_KP) { g_kp_score[row][rank] = si; g_kp_idx[row][rank] = ii; }
    }
    __syncthreads();
    if (kept < K_KP) {   // degenerate padding; won't trigger on this data
        for (int r2 = kept + tid; r2 < K_KP; r2 += 1024) {
            g_kp_score[row][r2] = -1.0f;
            g_kp_idx[row][r2]   = r2 - kept;
        }
    }
}

// Max-parallelism scattered gather: one thread per (row, channel, keypoint).
// 262144 threads, one isolated DRAM sector load each -> MLP across warps.
__global__ void gather_kernel(const float* __restrict__ d1s0, const float* __restrict__ d1s1,
                              const float* __restrict__ d2s0, const float* __restrict__ d2s1) {
    int row = blockIdx.y;
    int t   = blockIdx.x * blockDim.x + threadIdx.x;   // over C*K_KP, kpos fastest
    int ch  = t >> 9;
    int kp  = t & (K_KP - 1);
    int img = row >> 1, b = row & 1;

    int   idx = g_kp_idx[row][kp];      // coalesced (L2/L1 resident)
    float sc  = g_kp_score[row][kp];

    const float* dsc; int HW, p;
    if (idx < N0) { dsc = img ? d2s0 : d1s0; HW = N0; p = idx; }
    else          { dsc = img ? d2s1 : d1s1; HW = N1; p = idx - N0; }
    g_desc[row][ch][kp] = __ldg(&dsc[(b * C + ch) * HW + p]) * sc;

    if (ch < 2) {
        int W, pp; float scale;
        if (idx < N0) { W = W0; pp = idx;      scale = 1.0f; }
        else          { W = W1; pp = idx - N0; scale = 2.0f; }
        int r = pp / W, c = pp - r * W;
        g_loc[row][ch][kp] = (ch == 0 ? (float)r : (float)c) * scale;
    }
}

// apply Wq (rows 0,1) / Wk (rows 2,3) to contiguous g_desc
__global__ void wqk_kernel(const float* __restrict__ Wq, const float* __restrict__ Wk) {
    __shared__ float ds[C][17];
    int n0  = blockIdx.x * 16;
    int row = blockIdx.y;
    int tid = threadIdx.x;    // 128

    for (int i = tid; i < C * 16; i += 128) {
        int j = i >> 4, t = i & 15;
        ds[j][t] = g_desc[row][j][n0 + t];
    }
    __syncthreads();

    const float* Wm = (row < 2) ? Wq : Wk;
    float acc[16];
    #pragma unroll
    for (int t = 0; t < 16; ++t) acc[t] = 0.0f;
    const float* wrow = Wm + tid * C;
    #pragma unroll 4
    for (int j = 0; j < C; ++j) {
        float w = __ldg(&wrow[j]);
        #pragma unroll
        for (int t = 0; t < 16; ++t) acc[t] += w * ds[j][t];
    }
    #pragma unroll
    for (int t = 0; t < 16; ++t) g_qk[row][tid][n0 + t] = acc[t];
}

// rel[b][n][m] = sum_c q[b][c][n] * k[b][c][m]  (64x64 tiles, fp32)
__global__ void rel_kernel() {
    __shared__ float qs[32][64];
    __shared__ float ks2[32][64];
    int b  = blockIdx.z;
    int n0 = blockIdx.y * 64, m0 = blockIdx.x * 64;
    int tid = threadIdx.x;              // 256
    int tx = tid & 15, ty = tid >> 4;   // 16x16
    float acc[4][4];
    #pragma unroll
    for (int i = 0; i < 4; ++i)
        #pragma unroll
        for (int j = 0; j < 4; ++j) acc[i][j] = 0.0f;

    for (int c0 = 0; c0 < C; c0 += 32) {
        for (int i = tid; i < 32 * 64; i += 256) {
            int cc = i >> 6, nn = i & 63;
            qs[cc][nn]  = g_qk[b][c0 + cc][n0 + nn];
            ks2[cc][nn] = g_qk[2 + b][c0 + cc][m0 + nn];
        }
        __syncthreads();
        #pragma unroll
        for (int cc = 0; cc < 32; ++cc) {
            float qv[4], kv[4];
            #pragma unroll
            for (int i = 0; i < 4; ++i) qv[i] = qs[cc][ty * 4 + i];
            #pragma unroll
            for (int j = 0; j < 4; ++j) kv[j] = ks2[cc][tx * 4 + j];
            #pragma unroll
            for (int i = 0; i < 4; ++i)
                #pragma unroll
                for (int j = 0; j < 4; ++j) acc[i][j] += qv[i] * kv[j];
        }
        __syncthreads();
    }
    #pragma unroll
    for (int i = 0; i < 4; ++i)
        #pragma unroll
        for (int j = 0; j < 4; ++j)
            g_rel[b][n0 + ty * 4 + i][m0 + tx * 4 + j] = acc[i][j];
}

// per-row: top2 -> acos ratio; softmax(rel*512) weighted loc2 -> y
__global__ void match_kernel(const float* __restrict__ Wv) {
    int b    = blockIdx.y;
    int warp = threadIdx.x >> 5, lane = threadIdx.x & 31;
    int n = blockIdx.x * 8 + warp;
    const float* relrow = &g_rel[b][n][0];

    float m1 = -2.0f, m2 = -2.0f;
    for (int m = lane; m < K_KP; m += 32) {
        float v = relrow[m];
        if (v > m1) { m2 = m1; m1 = v; }
        else if (v > m2) m2 = v;
    }
    #pragma unroll
    for (int off = 16; off; off >>= 1) {
        float o1 = __shfl_down_sync(0xffffffffu, m1, off);
        float o2 = __shfl_down_sync(0xffffffffu, m2, off);
        if (o1 > m1) { m2 = fmaxf(m1, o2); m1 = o1; }
        else         { m2 = fmaxf(m2, o1); }
    }
    m1 = __shfl_sync(0xffffffffu, m1, 0);
    m2 = __shfl_sync(0xffffffffu, m2, 0);

    float wv00 = Wv[0], wv01 = Wv[1], wv10 = Wv[2], wv11 = Wv[3];
    int krow = 2 + b;
    float sw = 0.0f, y0 = 0.0f, y1 = 0.0f;
    for (int m = lane; m < K_KP; m += 32) {
        float v = relrow[m];
        float w = expf(INVTEMP * (v - m1));
        float l0 = g_loc[krow][0][m], l1 = g_loc[krow][1][m];
        sw += w;
        y0 += w * (wv00 * l0 + wv01 * l1);
        y1 += w * (wv10 * l0 + wv11 * l1);
    }
    #pragma unroll
    for (int off = 16; off; off >>= 1) {
        sw += __shfl_down_sync(0xffffffffu, sw, off);
        y0 += __shfl_down_sync(0xffffffffu, y0, off);
        y1 += __shfl_down_sync(0xffffffffu, y1, off);
    }
    if (lane == 0) {
        float a1 = acosf(fminf(fmaxf(m1, -1.0f), 1.0f));
        float a2 = acosf(fminf(fmaxf(m2, -1.0f), 1.0f));
        g_ratio[b][n] = a1 / a2;
        g_y[b][0][n] = y0 / sw;
        g_y[b][1][n] = y1 / sw;
    }
}

// final top-128 by smallest ratio (stable rank), write [B,4,128]
__global__ void final_kernel(float* __restrict__ out) {
    __shared__ float rs[K_KP];
    int b = blockIdx.x, tid = threadIdx.x;  // 512
    rs[tid] = g_ratio[b][tid];
    __syncthreads();
    float ri = rs[tid];
    int rank = 0;
    for (int j = 0; j < K_KP; ++j) {
        float rj = rs[j];
        rank += (rj < ri) || (rj == ri && j < tid);
    }
    if (rank < K_MATCH) {
        out[(b * 4 + 0) * K_MATCH + rank] = g_loc[b][0][tid];
        out[(b * 4 + 1) * K_MATCH + rank] = g_loc[b][1][tid];
        out[(b * 4 + 2) * K_MATCH + rank] = g_y[b][0][tid];
        out[(b * 4 + 3) * K_MATCH + rank] = g_y[b][1][tid];
    }
}

// ---------------- launch ----------------
extern "C" void kernel_launch(void* const* d_in, const int* in_sizes, int n_in,
                              void* d_out, int out_size) {
    const float* rep1_s0 = (const float*)d_in[0];
    const float* rel1_s0 = (const float*)d_in[1];
    const float* desc1_s0 = (const float*)d_in[2];
    const float* rep1_s1 = (const float*)d_in[3];
    const float* rel1_s1 = (const float*)d_in[4];
    const float* desc1_s1 = (const float*)d_in[5];
    const float* rep2_s0 = (const float*)d_in[6];
    const float* rel2_s0 = (const float*)d_in[7];
    const float* desc2_s0 = (const float*)d_in[8];
    const float* rep2_s1 = (const float*)d_in[9];
    const float* rel2_s1 = (const float*)d_in[10];
    const float* desc2_s1 = (const float*)d_in[11];
    const float* Wq = (const float*)d_in[12];
    const float* Wk = (const float*)d_in[13];
    const float* Wv = (const float*)d_in[14];
    float* out = (float*)d_out;

    // reset candidate counters as a memset graph node (no kernel launch)
    void* cntPtr = nullptr;
    cudaGetSymbolAddress(&cntPtr, g_cand_count);
    cudaMemsetAsync(cntPtr, 0, 4 * sizeof(int));

    score_all_kernel<<<dim3(W0 / 32, H0 / 8, 8), 256>>>(
        rep1_s0, rel1_s0, rep1_s1, rel1_s1, rep2_s0, rel2_s0, rep2_s1, rel2_s1);

    topk_kernel<<<4, 1024>>>();

    gather_kernel<<<dim3((C * K_KP) / 256, 4), 256>>>(desc1_s0, desc1_s1, desc2_s0, desc2_s1);

    wqk_kernel<<<dim3(K_KP / 16, 4), C>>>(Wq, Wk);

    rel_kernel<<<dim3(8, 8, B), 256>>>();

    match_kernel<<<dim3(K_KP / 8, B), 256>>>(Wv);

    final_kernel<<<B, K_KP>>>(out);
}

// round 4
// speedup vs baseline: 1.4789x; 1.0920x over previous
#include <cuda_runtime.h>
#include <math.h>

// ---------------- problem constants ----------------
#define B       2
#define C       128
#define H0      384
#define W0      512
#define H1      192
#define W1      256
#define N0      (H0*W0)     // 196608
#define N1      (H1*W1)     // 49152
#define K_KP    512
#define K_MATCH 128
#define CAP     32768
#define MKEEP   4096
#define THRESH  0.7f
#define INVTEMP 512.0f

// ---------------- device scratch ----------------
__device__ float g_cand_score[4][CAP];
__device__ int   g_cand_idx[4][CAP];
__device__ int   g_cand_count[4];
__device__ float g_kp_score[4][K_KP];
__device__ int   g_kp_idx[4][K_KP];
__device__ float g_desc[4][C][K_KP];   // gathered desc * score
__device__ float g_loc[4][2][K_KP];    // [row][{r,c}][k]
__device__ float g_qk[4][C][K_KP];     // rows 0,1 = q (img1), rows 2,3 = k (img2)
__device__ float g_rel[B][K_KP][K_KP];
__device__ float g_ratio[B][K_KP];
__device__ float g_y[B][2][K_KP];

// ---------------- kernels ----------------

// Fused score + 3x3 NMS over all 8 (img, scale, batch) slices.
// Block: 256 threads = 128x8 pixel tile (4 px/thread); smem halo tile;
// block-aggregated candidate append (one global atomic per block).
__global__ void score_all_kernel(const float* __restrict__ rep10, const float* __restrict__ rel10,
                                 const float* __restrict__ rep11, const float* __restrict__ rel11,
                                 const float* __restrict__ rep20, const float* __restrict__ rel20,
                                 const float* __restrict__ rep21, const float* __restrict__ rel21) {
    int z    = blockIdx.z;           // 0..7
    int img  = z >> 2;
    int scal = (z >> 1) & 1;
    int b    = z & 1;
    const float *rep, *rel;
    int H, W, nOff;
    if (scal == 0) { rep = img ? rep20 : rep10; rel = img ? rel20 : rel10; H = H0; W = W0; nOff = 0;  }
    else           { rep = img ? rep21 : rep11; rel = img ? rel21 : rel11; H = H1; W = W1; nOff = N0; }
    int gx0 = blockIdx.x * 128, gy0 = blockIdx.y * 8;
    if (gx0 >= W || gy0 >= H) return;
    int row = img * 2 + b;

    __shared__ float s[10][132];      // halo tile (130 cols used)
    __shared__ float c_sc[1024];
    __shared__ int   c_ix[1024];
    __shared__ int   c_cnt, c_base;

    int tid = threadIdx.x;
    const float* repb = rep + b * (H * W);
    const float* relb = rel + b * (H * W);

    if (tid == 0) c_cnt = 0;
    for (int i = tid; i < 10 * 132; i += 256) {
        int ly = i / 132, lx = i - ly * 132;
        if (lx < 130) {
            int gy = gy0 + ly - 1, gx = gx0 + lx - 1;
            float v = -INFINITY;
            if (gy >= 0 && gy < H && gx >= 0 && gx < W) v = repb[gy * W + gx];
            s[ly][lx] = v;
        }
    }
    __syncthreads();

    int tx = tid & 31, ty = tid >> 5;     // 32 x 8, 4 px/thread
    int gy = gy0 + ty;
    int cx = tx * 4;                       // local col base
    float4 e4 = *(const float4*)&relb[gy * W + gx0 + cx];
    float ev[4] = {e4.x, e4.y, e4.z, e4.w};
    #pragma unroll
    for (int px = 0; px < 4; ++px) {
        float v = s[ty + 1][cx + px + 1];
        float mean = sqrtf(v * ev[px]);
        if (mean >= THRESH) {
            float nb = fmaxf(fmaxf(s[ty][cx + px],     s[ty][cx + px + 1]),
                             fmaxf(s[ty][cx + px + 2], s[ty + 1][cx + px]));
            nb = fmaxf(nb, fmaxf(fmaxf(s[ty + 1][cx + px + 2], s[ty + 2][cx + px]),
                                 fmaxf(s[ty + 2][cx + px + 1], s[ty + 2][cx + px + 2])));
            if (!(nb > v)) {
                int p = atomicAdd(&c_cnt, 1);
                c_sc[p] = mean;
                c_ix[p] = nOff + gy * W + gx0 + cx + px;
            }
        }
    }
    __syncthreads();
    int cnt = c_cnt;
    if (cnt == 0) return;
    if (tid == 0) c_base = atomicAdd(&g_cand_count[row], cnt);
    __syncthreads();
    int base = c_base;
    for (int i = tid; i < cnt; i += 256) {
        int pos = base + i;
        if (pos < CAP) {
            g_cand_score[row][pos] = c_sc[i];
            g_cand_idx[row][pos]   = c_ix[i];
        }
    }
}

// per-row top-512: histogram prune then exact rank-count (jax top_k semantics:
// descending, ties -> lowest index first)
__global__ void topk_kernel() {
    __shared__ int   hist[1024];
    __shared__ float ks_[MKEEP];
    __shared__ int   ki_[MKEEP];
    __shared__ int   s_thr, s_keep;
    int row = blockIdx.x;
    int tid = threadIdx.x;              // 1024 threads
    int count = g_cand_count[row];
    if (count > CAP) count = CAP;

    hist[tid] = 0;
    if (tid == 0) { s_thr = 0; s_keep = 0; }
    __syncthreads();

    const float SCL = 1024.0f / 0.3f;
    for (int i = tid; i < count; i += 1024) {
        float sc = g_cand_score[row][i];
        int bb = (int)((sc - THRESH) * SCL);
        bb = max(0, min(1023, bb));
        atomicAdd(&hist[bb], 1);
    }
    __syncthreads();

    int cge = 0;
    for (int b2 = tid; b2 < 1024; ++b2) cge += hist[b2];
    int cge_next = cge - hist[tid];
    if (cge >= K_KP && cge_next < K_KP) s_thr = tid;   // unique writer
    __syncthreads();

    int thr = s_thr;
    for (int i = tid; i < count; i += 1024) {
        float sc = g_cand_score[row][i];
        int bb = (int)((sc - THRESH) * SCL);
        bb = max(0, min(1023, bb));
        if (bb >= thr) {
            int p = atomicAdd(&s_keep, 1);
            if (p < MKEEP) { ks_[p] = sc; ki_[p] = g_cand_idx[row][i]; }
        }
    }
    __syncthreads();
    int kept = min(s_keep, MKEEP);

    for (int i = tid; i < kept; i += 1024) {
        float si = ks_[i]; int ii = ki_[i];
        int rank = 0;
        for (int j = 0; j < kept; ++j) {
            float sj = ks_[j];
            rank += (sj > si) || (sj == si && ki_[j] < ii);
        }
        if (rank < K_KP) { g_kp_score[row][rank] = si; g_kp_idx[row][rank] = ii; }
    }
    __syncthreads();
    if (kept < K_KP) {   // degenerate padding; won't trigger on this data
        for (int r2 = kept + tid; r2 < K_KP; r2 += 1024) {
            g_kp_score[row][r2] = -1.0f;
            g_kp_idx[row][r2]   = r2 - kept;
        }
    }
}

// Max-parallelism scattered gather: one thread per (row, channel, keypoint).
__global__ void gather_kernel(const float* __restrict__ d1s0, const float* __restrict__ d1s1,
                              const float* __restrict__ d2s0, const float* __restrict__ d2s1) {
    int row = blockIdx.y;
    int t   = blockIdx.x * blockDim.x + threadIdx.x;   // over C*K_KP, kpos fastest
    int ch  = t >> 9;
    int kp  = t & (K_KP - 1);
    int img = row >> 1, b = row & 1;

    int   idx = g_kp_idx[row][kp];      // coalesced (L2/L1 resident)
    float sc  = g_kp_score[row][kp];

    const float* dsc; int HW, p;
    if (idx < N0) { dsc = img ? d2s0 : d1s0; HW = N0; p = idx; }
    else          { dsc = img ? d2s1 : d1s1; HW = N1; p = idx - N0; }
    g_desc[row][ch][kp] = __ldg(&dsc[(b * C + ch) * HW + p]) * sc;

    if (ch < 2) {
        int W, pp; float scale;
        if (idx < N0) { W = W0; pp = idx;      scale = 1.0f; }
        else          { W = W1; pp = idx - N0; scale = 2.0f; }
        int r = pp / W, c = pp - r * W;
        g_loc[row][ch][kp] = (ch == 0 ? (float)r : (float)c) * scale;
    }
}

// apply Wq (rows 0,1) / Wk (rows 2,3) as tiled GEMM:
// g_qk[row][r][n] = sum_c Wm[r][c] * g_desc[row][c][n]
// 64x64 output tile per block, 16x16 threads x 4x4 regs; c ascending (bit-stable).
__global__ void wqk_kernel(const float* __restrict__ Wq, const float* __restrict__ Wk) {
    __shared__ float ws[32][65];   // [c][r] transposed tile
    __shared__ float ds[32][64];   // [c][n]
    int row = blockIdx.z;
    int n0 = blockIdx.x * 64, r0 = blockIdx.y * 64;
    const float* Wm = (row < 2) ? Wq : Wk;
    int tid = threadIdx.x;              // 256
    int tx = tid & 15, ty = tid >> 4;   // 16x16
    float acc[4][4];
    #pragma unroll
    for (int i = 0; i < 4; ++i)
        #pragma unroll
        for (int j = 0; j < 4; ++j) acc[i][j] = 0.0f;

    for (int c0 = 0; c0 < C; c0 += 32) {
        for (int i = tid; i < 64 * 32; i += 256) {
            int rr = i >> 5, cc = i & 31;          // coalesced over cc
            ws[cc][rr] = Wm[(r0 + rr) * C + c0 + cc];
        }
        for (int i = tid; i < 32 * 64; i += 256) {
            int cc = i >> 6, nn = i & 63;          // coalesced over nn
            ds[cc][nn] = g_desc[row][c0 + cc][n0 + nn];
        }
        __syncthreads();
        #pragma unroll
        for (int cc = 0; cc < 32; ++cc) {
            float wv[4], dv[4];
            #pragma unroll
            for (int i = 0; i < 4; ++i) wv[i] = ws[cc][ty * 4 + i];
            #pragma unroll
            for (int j = 0; j < 4; ++j) dv[j] = ds[cc][tx * 4 + j];
            #pragma unroll
            for (int i = 0; i < 4; ++i)
                #pragma unroll
                for (int j = 0; j < 4; ++j) acc[i][j] += wv[i] * dv[j];
        }
        __syncthreads();
    }
    #pragma unroll
    for (int i = 0; i < 4; ++i)
        #pragma unroll
        for (int j = 0; j < 4; ++j)
            g_qk[row][r0 + ty * 4 + i][n0 + tx * 4 + j] = acc[i][j];
}

// rel[b][n][m] = sum_c q[b][c][n] * k[b][c][m]  (64x64 tiles, fp32)
__global__ void rel_kernel() {
    __shared__ float qs[32][64];
    __shared__ float ks2[32][64];
    int b  = blockIdx.z;
    int n0 = blockIdx.y * 64, m0 = blockIdx.x * 64;
    int tid = threadIdx.x;              // 256
    int tx = tid & 15, ty = tid >> 4;   // 16x16
    float acc[4][4];
    #pragma unroll
    for (int i = 0; i < 4; ++i)
        #pragma unroll
        for (int j = 0; j < 4; ++j) acc[i][j] = 0.0f;

    for (int c0 = 0; c0 < C; c0 += 32) {
        for (int i = tid; i < 32 * 64; i += 256) {
            int cc = i >> 6, nn = i & 63;
            qs[cc][nn]  = g_qk[b][c0 + cc][n0 + nn];
            ks2[cc][nn] = g_qk[2 + b][c0 + cc][m0 + nn];
        }
        __syncthreads();
        #pragma unroll
        for (int cc = 0; cc < 32; ++cc) {
            float qv[4], kv[4];
            #pragma unroll
            for (int i = 0; i < 4; ++i) qv[i] = qs[cc][ty * 4 + i];
            #pragma unroll
            for (int j = 0; j < 4; ++j) kv[j] = ks2[cc][tx * 4 + j];
            #pragma unroll
            for (int i = 0; i < 4; ++i)
                #pragma unroll
                for (int j = 0; j < 4; ++j) acc[i][j] += qv[i] * kv[j];
        }
        __syncthreads();
    }
    #pragma unroll
    for (int i = 0; i < 4; ++i)
        #pragma unroll
        for (int j = 0; j < 4; ++j)
            g_rel[b][n0 + ty * 4 + i][m0 + tx * 4 + j] = acc[i][j];
}

// per-row: top2 -> acos ratio; softmax(rel*512) weighted loc2 -> y
__global__ void match_kernel(const float* __restrict__ Wv) {
    int b    = blockIdx.y;
    int warp = threadIdx.x >> 5, lane = threadIdx.x & 31;
    int n = blockIdx.x * 8 + warp;
    const float* relrow = &g_rel[b][n][0];

    float m1 = -2.0f, m2 = -2.0f;
    for (int m = lane; m < K_KP; m += 32) {
        float v = relrow[m];
        if (v > m1) { m2 = m1; m1 = v; }
        else if (v > m2) m2 = v;
    }
    #pragma unroll
    for (int off = 16; off; off >>= 1) {
        float o1 = __shfl_down_sync(0xffffffffu, m1, off);
        float o2 = __shfl_down_sync(0xffffffffu, m2, off);
        if (o1 > m1) { m2 = fmaxf(m1, o2); m1 = o1; }
        else         { m2 = fmaxf(m2, o1); }
    }
    m1 = __shfl_sync(0xffffffffu, m1, 0);
    m2 = __shfl_sync(0xffffffffu, m2, 0);

    float wv00 = Wv[0], wv01 = Wv[1], wv10 = Wv[2], wv11 = Wv[3];
    int krow = 2 + b;
    float sw = 0.0f, y0 = 0.0f, y1 = 0.0f;
    for (int m = lane; m < K_KP; m += 32) {
        float v = relrow[m];
        float w = expf(INVTEMP * (v - m1));
        float l0 = g_loc[krow][0][m], l1 = g_loc[krow][1][m];
        sw += w;
        y0 += w * (wv00 * l0 + wv01 * l1);
        y1 += w * (wv10 * l0 + wv11 * l1);
    }
    #pragma unroll
    for (int off = 16; off; off >>= 1) {
        sw += __shfl_down_sync(0xffffffffu, sw, off);
        y0 += __shfl_down_sync(0xffffffffu, y0, off);
        y1 += __shfl_down_sync(0xffffffffu, y1, off);
    }
    if (lane == 0) {
        float a1 = acosf(fminf(fmaxf(m1, -1.0f), 1.0f));
        float a2 = acosf(fminf(fmaxf(m2, -1.0f), 1.0f));
        g_ratio[b][n] = a1 / a2;
        g_y[b][0][n] = y0 / sw;
        g_y[b][1][n] = y1 / sw;
    }
}

// final top-128 by smallest ratio (stable rank), write [B,4,128]
__global__ void final_kernel(float* __restrict__ out) {
    __shared__ float rs[K_KP];
    int b = blockIdx.x, tid = threadIdx.x;  // 512
    rs[tid] = g_ratio[b][tid];
    __syncthreads();
    float ri = rs[tid];
    int rank = 0;
    for (int j = 0; j < K_KP; ++j) {
        float rj = rs[j];
        rank += (rj < ri) || (rj == ri && j < tid);
    }
    if (rank < K_MATCH) {
        out[(b * 4 + 0) * K_MATCH + rank] = g_loc[b][0][tid];
        out[(b * 4 + 1) * K_MATCH + rank] = g_loc[b][1][tid];
        out[(b * 4 + 2) * K_MATCH + rank] = g_y[b][0][tid];
        out[(b * 4 + 3) * K_MATCH + rank] = g_y[b][1][tid];
    }
}

// ---------------- launch ----------------
extern "C" void kernel_launch(void* const* d_in, const int* in_sizes, int n_in,
                              void* d_out, int out_size) {
    const float* rep1_s0 = (const float*)d_in[0];
    const float* rel1_s0 = (const float*)d_in[1];
    const float* desc1_s0 = (const float*)d_in[2];
    const float* rep1_s1 = (const float*)d_in[3];
    const float* rel1_s1 = (const float*)d_in[4];
    const float* desc1_s1 = (const float*)d_in[5];
    const float* rep2_s0 = (const float*)d_in[6];
    const float* rel2_s0 = (const float*)d_in[7];
    const float* desc2_s0 = (const float*)d_in[8];
    const float* rep2_s1 = (const float*)d_in[9];
    const float* rel2_s1 = (const float*)d_in[10];
    const float* desc2_s1 = (const float*)d_in[11];
    const float* Wq = (const float*)d_in[12];
    const float* Wk = (const float*)d_in[13];
    const float* Wv = (const float*)d_in[14];
    float* out = (float*)d_out;

    // reset candidate counters as a memset graph node (no kernel launch)
    void* cntPtr = nullptr;
    cudaGetSymbolAddress(&cntPtr, g_cand_count);
    cudaMemsetAsync(cntPtr, 0, 4 * sizeof(int));

    score_all_kernel<<<dim3(W0 / 128, H0 / 8, 8), 256>>>(
        rep1_s0, rel1_s0, rep1_s1, rel1_s1, rep2_s0, rel2_s0, rep2_s1, rel2_s1);

    topk_kernel<<<4, 1024>>>();

    gather_kernel<<<dim3((C * K_KP) / 256, 4), 256>>>(desc1_s0, desc1_s1, desc2_s0, desc2_s1);

    wqk_kernel<<<dim3(K_KP / 64, C / 64, 4), 256>>>(Wq, Wk);

    rel_kernel<<<dim3(8, 8, B), 256>>>();

    match_kernel<<<dim3(K_KP / 8, B), 256>>>(Wv);

    final_kernel<<<B, K_KP>>>(out);
}

// round 6
// speedup vs baseline: 1.5105x; 1.0214x over previous
#include <cuda_runtime.h>
#include <math.h>

// ---------------- problem constants ----------------
#define B       2
#define C       128
#define H0      384
#define W0      512
#define H1      192
#define W1      256
#define N0      (H0*W0)     // 196608
#define N1      (H1*W1)     // 49152
#define K_KP    512
#define K_MATCH 128
#define CAP     32768
#define MKEEP   4096
#define THRESH  0.7f
#define INVTEMP 512.0f

// ---------------- device scratch ----------------
__device__ float g_cand_score[4][CAP];
__device__ int   g_cand_idx[4][CAP];
__device__ int   g_cand_count[4];          // zero-initialized; re-zeroed each run by gather
__device__ float g_kp_score[4][K_KP];
__device__ int   g_kp_idx[4][K_KP];
__device__ float g_desc[4][C][K_KP];       // gathered desc * score
__device__ float g_loc[4][2][K_KP];        // [row][{r,c}][k]
__device__ float g_M[C][C];                // Wq^T * Wk
__device__ float g_T[B][C][K_KP];          // M @ d2  (k-side transformed)
__device__ float g_rel[B][K_KP][K_KP];
__device__ float g_ratio[B][K_KP];
__device__ float g_y[B][2][K_KP];

// ---------------- kernels ----------------

// Fused score + 3x3 NMS over all 8 (img, scale, batch) slices.
__global__ void score_all_kernel(const float* __restrict__ rep10, const float* __restrict__ rel10,
                                 const float* __restrict__ rep11, const float* __restrict__ rel11,
                                 const float* __restrict__ rep20, const float* __restrict__ rel20,
                                 const float* __restrict__ rep21, const float* __restrict__ rel21) {
    int z    = blockIdx.z;           // 0..7
    int img  = z >> 2;
    int scal = (z >> 1) & 1;
    int b    = z & 1;
    const float *rep, *rel;
    int H, W, nOff;
    if (scal == 0) { rep = img ? rep20 : rep10; rel = img ? rel20 : rel10; H = H0; W = W0; nOff = 0;  }
    else           { rep = img ? rep21 : rep11; rel = img ? rel21 : rel11; H = H1; W = W1; nOff = N0; }
    int gx0 = blockIdx.x * 128, gy0 = blockIdx.y * 8;
    if (gx0 >= W || gy0 >= H) return;
    int row = img * 2 + b;

    __shared__ float s[10][132];
    __shared__ float c_sc[1024];
    __shared__ int   c_ix[1024];
    __shared__ int   c_cnt, c_base;

    int tid = threadIdx.x;
    const float* repb = rep + b * (H * W);
    const float* relb = rel + b * (H * W);

    if (tid == 0) c_cnt = 0;
    for (int i = tid; i < 10 * 132; i += 256) {
        int ly = i / 132, lx = i - ly * 132;
        if (lx < 130) {
            int gy = gy0 + ly - 1, gx = gx0 + lx - 1;
            float v = -INFINITY;
            if (gy >= 0 && gy < H && gx >= 0 && gx < W) v = repb[gy * W + gx];
            s[ly][lx] = v;
        }
    }
    __syncthreads();

    int tx = tid & 31, ty = tid >> 5;     // 32 x 8, 4 px/thread
    int gy = gy0 + ty;
    int cx = tx * 4;
    float4 e4 = *(const float4*)&relb[gy * W + gx0 + cx];
    float ev[4] = {e4.x, e4.y, e4.z, e4.w};
    #pragma unroll
    for (int px = 0; px < 4; ++px) {
        float v = s[ty + 1][cx + px + 1];
        float mean = sqrtf(v * ev[px]);
        if (mean >= THRESH) {
            float nb = fmaxf(fmaxf(s[ty][cx + px],     s[ty][cx + px + 1]),
                             fmaxf(s[ty][cx + px + 2], s[ty + 1][cx + px]));
            nb = fmaxf(nb, fmaxf(fmaxf(s[ty + 1][cx + px + 2], s[ty + 2][cx + px]),
                                 fmaxf(s[ty + 2][cx + px + 1], s[ty + 2][cx + px + 2])));
            if (!(nb > v)) {
                int p = atomicAdd(&c_cnt, 1);
                c_sc[p] = mean;
                c_ix[p] = nOff + gy * W + gx0 + cx + px;
            }
        }
    }
    __syncthreads();
    int cnt = c_cnt;
    if (cnt == 0) return;
    if (tid == 0) c_base = atomicAdd(&g_cand_count[row], cnt);
    __syncthreads();
    int base = c_base;
    for (int i = tid; i < cnt; i += 256) {
        int pos = base + i;
        if (pos < CAP) {
            g_cand_score[row][pos] = c_sc[i];
            g_cand_idx[row][pos]   = c_ix[i];
        }
    }
}

// per-row top-512: histogram prune then exact rank-count (jax top_k semantics)
__global__ void topk_kernel() {
    __shared__ int   hist[1024];
    __shared__ float ks_[MKEEP];
    __shared__ int   ki_[MKEEP];
    __shared__ int   s_thr, s_keep;
    int row = blockIdx.x;
    int tid = threadIdx.x;              // 1024 threads
    int count = g_cand_count[row];
    if (count > CAP) count = CAP;

    hist[tid] = 0;
    if (tid == 0) { s_thr = 0; s_keep = 0; }
    __syncthreads();

    const float SCL = 1024.0f / 0.3f;
    for (int i = tid; i < count; i += 1024) {
        float sc = g_cand_score[row][i];
        int bb = (int)((sc - THRESH) * SCL);
        bb = max(0, min(1023, bb));
        atomicAdd(&hist[bb], 1);
    }
    __syncthreads();

    int cge = 0;
    for (int b2 = tid; b2 < 1024; ++b2) cge += hist[b2];
    int cge_next = cge - hist[tid];
    if (cge >= K_KP && cge_next < K_KP) s_thr = tid;   // unique writer
    __syncthreads();

    int thr = s_thr;
    for (int i = tid; i < count; i += 1024) {
        float sc = g_cand_score[row][i];
        int bb = (int)((sc - THRESH) * SCL);
        bb = max(0, min(1023, bb));
        if (bb >= thr) {
            int p = atomicAdd(&s_keep, 1);
            if (p < MKEEP) { ks_[p] = sc; ki_[p] = g_cand_idx[row][i]; }
        }
    }
    __syncthreads();
    int kept = min(s_keep, MKEEP);

    for (int i = tid; i < kept; i += 1024) {
        float si = ks_[i]; int ii = ki_[i];
        int rank = 0;
        for (int j = 0; j < kept; ++j) {
            float sj = ks_[j];
            rank += (sj > si) || (sj == si && ki_[j] < ii);
        }
        if (rank < K_KP) { g_kp_score[row][rank] = si; g_kp_idx[row][rank] = ii; }
    }
    __syncthreads();
    if (kept < K_KP) {
        for (int r2 = kept + tid; r2 < K_KP; r2 += 1024) {
            g_kp_score[row][r2] = -1.0f;
            g_kp_idx[row][r2]   = r2 - kept;
        }
    }
}

// Merged launch: blocks [0,1024): scattered gather for all 4 rows (+ counter
// reset); blocks [1024,1040): compute M = Wq^T @ Wk in 32x32 tiles.
__global__ void gather_matM_kernel(const float* __restrict__ d1s0, const float* __restrict__ d1s1,
                                   const float* __restrict__ d2s0, const float* __restrict__ d2s1,
                                   const float* __restrict__ Wq,  const float* __restrict__ Wk) {
    int bid = blockIdx.x;
    if (bid < 1024) {
        if (bid == 0 && threadIdx.x < 4) g_cand_count[threadIdx.x] = 0;  // reset for next run
        int row = bid >> 8;                               // 256 blocks per row
        int t   = (bid & 255) * 256 + threadIdx.x;        // over C*K_KP, kpos fastest
        int ch  = t >> 9;
        int kp  = t & (K_KP - 1);
        int img = row >> 1, b = row & 1;

        int   idx = g_kp_idx[row][kp];
        float sc  = g_kp_score[row][kp];

        const float* dsc; int HW, p;
        if (idx < N0) { dsc = img ? d2s0 : d1s0; HW = N0; p = idx; }
        else          { dsc = img ? d2s1 : d1s1; HW = N1; p = idx - N0; }
        g_desc[row][ch][kp] = __ldg(&dsc[(b * C + ch) * HW + p]) * sc;

        if (ch < 2) {
            int W, pp; float scale;
            if (idx < N0) { W = W0; pp = idx;      scale = 1.0f; }
            else          { W = W1; pp = idx - N0; scale = 2.0f; }
            int r = pp / W, c = pp - r * W;
            g_loc[row][ch][kp] = (ch == 0 ? (float)r : (float)c) * scale;
        }
    } else {
        // M[c1][c2] = sum_r Wq[r][c1] * Wk[r][c2]; 32x32 tile per block
        int mb = bid - 1024;                 // 0..15
        int c1_0 = (mb >> 2) * 32, c2_0 = (mb & 3) * 32;
        __shared__ float wqs[32][33];        // [r][c1]
        __shared__ float wks[32][33];        // [r][c2]
        int tid = threadIdx.x;               // 256
        int c1l = tid >> 3;                  // 0..31
        int c2q = (tid & 7) * 4;             // 0,4,...,28
        float acc[4] = {0.f, 0.f, 0.f, 0.f};
        for (int r0 = 0; r0 < C; r0 += 32) {
            for (int i = tid; i < 32 * 32; i += 256) {
                int rr = i >> 5, cc = i & 31;
                wqs[rr][cc] = Wq[(r0 + rr) * C + c1_0 + cc];
                wks[rr][cc] = Wk[(r0 + rr) * C + c2_0 + cc];
            }
            __syncthreads();
            #pragma unroll
            for (int rr = 0; rr < 32; ++rr) {
                float wq = wqs[rr][c1l];
                #pragma unroll
                for (int j = 0; j < 4; ++j) acc[j] += wq * wks[rr][c2q + j];
            }
            __syncthreads();
        }
        #pragma unroll
        for (int j = 0; j < 4; ++j) g_M[c1_0 + c1l][c2_0 + c2q + j] = acc[j];
    }
}

// T[b] = M @ g_desc[2+b] : 16r x 64n tiles, grid (8, 8, 2)
__global__ void tk_kernel() {
    __shared__ float ms[32][17];   // [c][r]
    __shared__ float ds[32][64];   // [c][n]
    int n0 = blockIdx.x * 64, r0 = blockIdx.y * 16, b = blockIdx.z;
    int krow = 2 + b;
    int tid = threadIdx.x;              // 256
    int tx = tid & 15, ty = tid >> 4;   // 16x16: tx -> n quad, ty -> r
    float acc[4] = {0.f, 0.f, 0.f, 0.f};

    for (int c0 = 0; c0 < C; c0 += 32) {
        for (int i = tid; i < 16 * 32; i += 256) {
            int rr = i >> 5, cc = i & 31;
            ms[cc][rr] = g_M[r0 + rr][c0 + cc];
        }
        for (int i = tid; i < 32 * 64; i += 256) {
            int cc = i >> 6, nn = i & 63;
            ds[cc][nn] = g_desc[krow][c0 + cc][n0 + nn];
        }
        __syncthreads();
        #pragma unroll
        for (int cc = 0; cc < 32; ++cc) {
            float w = ms[cc][ty];
            float4 dv = *(const float4*)&ds[cc][tx * 4];
            acc[0] += w * dv.x; acc[1] += w * dv.y;
            acc[2] += w * dv.z; acc[3] += w * dv.w;
        }
        __syncthreads();
    }
    #pragma unroll
    for (int j = 0; j < 4; ++j) g_T[b][r0 + ty][n0 + tx * 4 + j] = acc[j];
}

// rel[b][n][m] = sum_c d1[b][c][n] * T[b][c][m]  (64x64 tiles, float4 LDS)
__global__ void rel_kernel() {
    __shared__ float qs[32][64];
    __shared__ float ks2[32][64];
    int b  = blockIdx.z;
    int n0 = blockIdx.y * 64, m0 = blockIdx.x * 64;
    int tid = threadIdx.x;              // 256
    int tx = tid & 15, ty = tid >> 4;   // 16x16
    float acc[4][4];
    #pragma unroll
    for (int i = 0; i < 4; ++i)
        #pragma unroll
        for (int j = 0; j < 4; ++j) acc[i][j] = 0.0f;

    for (int c0 = 0; c0 < C; c0 += 32) {
        for (int i = tid; i < 32 * 64; i += 256) {
            int cc = i >> 6, nn = i & 63;
            qs[cc][nn]  = g_desc[b][c0 + cc][n0 + nn];
            ks2[cc][nn] = g_T[b][c0 + cc][m0 + nn];
        }
        __syncthreads();
        #pragma unroll
        for (int cc = 0; cc < 32; ++cc) {
            float4 qv = *(const float4*)&qs[cc][ty * 4];
            float4 kv = *(const float4*)&ks2[cc][tx * 4];
            float qa[4] = {qv.x, qv.y, qv.z, qv.w};
            float ka[4] = {kv.x, kv.y, kv.z, kv.w};
            #pragma unroll
            for (int i = 0; i < 4; ++i)
                #pragma unroll
                for (int j = 0; j < 4; ++j) acc[i][j] += qa[i] * ka[j];
        }
        __syncthreads();
    }
    #pragma unroll
    for (int i = 0; i < 4; ++i)
        #pragma unroll
        for (int j = 0; j < 4; ++j)
            g_rel[b][n0 + ty * 4 + i][m0 + tx * 4 + j] = acc[i][j];
}

// per-row: one-pass top2 + acos ratio + softmax-weighted loc (grid: 64 x B)
__global__ void match_kernel(const float* __restrict__ Wv) {
    int b    = blockIdx.y;
    int warp = threadIdx.x >> 5, lane = threadIdx.x & 31;
    int n = blockIdx.x * 8 + warp;
    const float* relrow = &g_rel[b][n][0];

    float v[16];
    #pragma unroll
    for (int t = 0; t < 16; ++t) v[t] = relrow[lane + 32 * t];

    float m1 = -2.0f, m2 = -2.0f;
    #pragma unroll
    for (int t = 0; t < 16; ++t) {
        float x = v[t];
        if (x > m1) { m2 = m1; m1 = x; }
        else if (x > m2) m2 = x;
    }
    #pragma unroll
    for (int off = 16; off; off >>= 1) {
        float o1 = __shfl_down_sync(0xffffffffu, m1, off);
        float o2 = __shfl_down_sync(0xffffffffu, m2, off);
        if (o1 > m1) { m2 = fmaxf(m1, o2); m1 = o1; }
        else         { m2 = fmaxf(m2, o1); }
    }
    m1 = __shfl_sync(0xffffffffu, m1, 0);
    m2 = __shfl_sync(0xffffffffu, m2, 0);

    float wv00 = Wv[0], wv01 = Wv[1], wv10 = Wv[2], wv11 = Wv[3];
    int krow = 2 + b;
    float sw = 0.0f, y0 = 0.0f, y1 = 0.0f;
    #pragma unroll
    for (int t = 0; t < 16; ++t) {
        int m = lane + 32 * t;
        float w = expf(INVTEMP * (v[t] - m1));
        float l0 = g_loc[krow][0][m], l1 = g_loc[krow][1][m];
        sw += w;
        y0 += w * (wv00 * l0 + wv01 * l1);
        y1 += w * (wv10 * l0 + wv11 * l1);
    }
    #pragma unroll
    for (int off = 16; off; off >>= 1) {
        sw += __shfl_down_sync(0xffffffffu, sw, off);
        y0 += __shfl_down_sync(0xffffffffu, y0, off);
        y1 += __shfl_down_sync(0xffffffffu, y1, off);
    }
    if (lane == 0) {
        float a1 = acosf(fminf(fmaxf(m1, -1.0f), 1.0f));
        float a2 = acosf(fminf(fmaxf(m2, -1.0f), 1.0f));
        g_ratio[b][n] = a1 / a2;
        g_y[b][0][n] = y0 / sw;
        g_y[b][1][n] = y1 / sw;
    }
}

// final top-128 by smallest ratio (stable rank), write [B,4,128]
__global__ void final_kernel(float* __restrict__ out) {
    __shared__ float rs[K_KP];
    int b = blockIdx.x, tid = threadIdx.x;  // 512
    rs[tid] = g_ratio[b][tid];
    __syncthreads();
    float ri = rs[tid];
    int rank = 0;
    for (int j = 0; j < K_KP; ++j) {
        float rj = rs[j];
        rank += (rj < ri) || (rj == ri && j < tid);
    }
    if (rank < K_MATCH) {
        out[(b * 4 + 0) * K_MATCH + rank] = g_loc[b][0][tid];
        out[(b * 4 + 1) * K_MATCH + rank] = g_loc[b][1][tid];
        out[(b * 4 + 2) * K_MATCH + rank] = g_y[b][0][tid];
        out[(b * 4 + 3) * K_MATCH + rank] = g_y[b][1][tid];
    }
}

// ---------------- launch ----------------
extern "C" void kernel_launch(void* const* d_in, const int* in_sizes, int n_in,
                              void* d_out, int out_size) {
    const float* rep1_s0 = (const float*)d_in[0];
    const float* rel1_s0 = (const float*)d_in[1];
    const float* desc1_s0 = (const float*)d_in[2];
    const float* rep1_s1 = (const float*)d_in[3];
    const float* rel1_s1 = (const float*)d_in[4];
    const float* desc1_s1 = (const float*)d_in[5];
    const float* rep2_s0 = (const float*)d_in[6];
    const float* rel2_s0 = (const float*)d_in[7];
    const float* desc2_s0 = (const float*)d_in[8];
    const float* rep2_s1 = (const float*)d_in[9];
    const float* rel2_s1 = (const float*)d_in[10];
    const float* desc2_s1 = (const float*)d_in[11];
    const float* Wq = (const float*)d_in[12];
    const float* Wk = (const float*)d_in[13];
    const float* Wv = (const float*)d_in[14];
    float* out = (float*)d_out;

    score_all_kernel<<<dim3(W0 / 128, H0 / 8, 8), 256>>>(
        rep1_s0, rel1_s0, rep1_s1, rel1_s1, rep2_s0, rel2_s0, rep2_s1, rel2_s1);

    topk_kernel<<<4, 1024>>>();

    gather_matM_kernel<<<1040, 256>>>(desc1_s0, desc1_s1, desc2_s0, desc2_s1, Wq, Wk);

    tk_kernel<<<dim3(8, 8, 2), 256>>>();

    rel_kernel<<<dim3(8, 8, B), 256>>>();

    match_kernel<<<dim3(K_KP / 8, B), 256>>>(Wv);

    final_kernel<<<B, K_KP>>>(out);
}